// round 5
// baseline (speedup 1.0000x reference)
#include <cuda_runtime.h>

typedef unsigned long long u64;

#define DEVINL __device__ __forceinline__

DEVINL u64 pack2(float lo, float hi) {
    u64 r; asm("mov.b64 %0, {%1,%2};" : "=l"(r) : "f"(lo), "f"(hi)); return r;
}
DEVINL void unpack2(u64 v, float& lo, float& hi) {
    asm("mov.b64 {%0,%1}, %2;" : "=f"(lo), "=f"(hi) : "l"(v));
}
DEVINL u64 ffma2(u64 a, u64 b, u64 c) {
    u64 d; asm("fma.rn.f32x2 %0, %1, %2, %3;" : "=l"(d) : "l"(a), "l"(b), "l"(c)); return d;
}
DEVINL float fast_sigmoid(float x) {
    float e = -1.4426950408889634f * x;   // -x * log2(e)
    float t; asm("ex2.approx.f32 %0, %1;" : "=f"(t) : "f"(e));
    float s = 1.0f + t;
    float r; asm("rcp.approx.f32 %0, %1;" : "=f"(r) : "f"(s));
    return r;
}

static constexpr int Bsz  = 64;
static constexpr int Kc   = 16;
static constexpr int HW   = 784;    // 28*28
static constexpr int PQ   = 1024;   // 32*32
static constexpr int THREADS   = 128;
static constexpr int PQ_TILE   = 512;   // per CTA (half of PQ)
static constexpr int CH        = 64;    // hw per CTA
static constexpr int HW_PER_IT = 16;    // 4 warps * 4 hw per iteration
static constexpr int UH        = 4;     // hw register-block per warp

__global__ __launch_bounds__(THREADS)
void fused_vaw_sigmoid_kernel(
    const float* __restrict__ V,      // [B,K,HW]
    const float* __restrict__ A,      // [B,K,PQ]
    const float* __restrict__ w,      // [K]
    const float* __restrict__ bias_p, // [1]
    float* __restrict__ out)          // [B,HW,PQ]
{
    __shared__ u64 sA[Kc][PQ_TILE / 2];  // w_k * A, stored as f32x2 pairs: 32 KB
    __shared__ u64 sV[CH * Kc];          // V duplicated (v,v) pairs: 8 KB

    const int tid  = threadIdx.x;
    const int lane = tid & 31;
    const int wrp  = tid >> 5;
    const int b    = blockIdx.z;
    const int pq0  = blockIdx.y * PQ_TILE;
    const int hw0  = blockIdx.x * CH;
    const float bias = __ldg(bias_p);

    // ---- stage w_k * A[b,k,pq0:pq0+512] into smem as f32x2 pairs ----
    {
        const float4* A4 = reinterpret_cast<const float4*>(A);
        #pragma unroll
        for (int k = 0; k < Kc; ++k) {
            float wk = __ldg(w + k);
            float4 a = __ldg(&A4[(size_t)(b * Kc + k) * (PQ / 4) + (pq0 >> 2) + tid]);
            a.x *= wk; a.y *= wk; a.z *= wk; a.w *= wk;
            u64* dst = &sA[k][tid * 2];
            dst[0] = pack2(a.x, a.y);
            dst[1] = pack2(a.z, a.w);
        }
    }
    // ---- stage V[b,:,hw0:hw0+64] duplicated into smem ----
    for (int idx = tid; idx < CH * Kc; idx += THREADS) {
        int kk  = idx & (Kc - 1);
        int hwl = idx >> 4;
        int hw  = hw0 + hwl;
        float v = (hw < HW) ? __ldg(&V[(size_t)(b * Kc + kk) * HW + hw]) : 0.0f;
        sV[hwl * Kc + kk] = pack2(v, v);
    }
    __syncthreads();

    const u64 bias2 = pack2(bias, bias);
    const int hw_rem = HW - hw0;
    const int chunk  = (hw_rem < CH) ? hw_rem : CH;
    const int n_it   = (chunk + HW_PER_IT - 1) / HW_PER_IT;

    for (int it = 0; it < n_it; ++it) {
        const int hwl0 = it * HW_PER_IT + wrp * UH;

        u64 acc[UH][4][2];
        #pragma unroll
        for (int u = 0; u < UH; ++u)
            #pragma unroll
            for (int g = 0; g < 4; ++g) {
                acc[u][g][0] = bias2;
                acc[u][g][1] = bias2;
            }

        #pragma unroll
        for (int c = 0; c < 4; ++c) {
            u64 vv[UH][4];
            #pragma unroll
            for (int u = 0; u < UH; ++u)
                #pragma unroll
                for (int j = 0; j < 4; ++j)
                    vv[u][j] = sV[(hwl0 + u) * Kc + c * 4 + j];

            #pragma unroll
            for (int j = 0; j < 4; ++j) {
                const u64* row = sA[c * 4 + j];
                #pragma unroll
                for (int g = 0; g < 4; ++g) {
                    ulonglong2 a2 =
                        *reinterpret_cast<const ulonglong2*>(&row[g * 64 + lane * 2]);
                    #pragma unroll
                    for (int u = 0; u < UH; ++u) {
                        acc[u][g][0] = ffma2(vv[u][j], a2.x, acc[u][g][0]);
                        acc[u][g][1] = ffma2(vv[u][j], a2.y, acc[u][g][1]);
                    }
                }
            }
        }

        // ---- epilogue: sigmoid + coalesced STG.128 ----
        #pragma unroll
        for (int u = 0; u < UH; ++u) {
            int hw = hw0 + hwl0 + u;
            if (hw < HW) {
                float4* op = reinterpret_cast<float4*>(
                    out + (size_t)(b * HW + hw) * PQ + pq0);
                #pragma unroll
                for (int g = 0; g < 4; ++g) {
                    float x0, x1, x2, x3;
                    unpack2(acc[u][g][0], x0, x1);
                    unpack2(acc[u][g][1], x2, x3);
                    float4 r;
                    r.x = fast_sigmoid(x0);
                    r.y = fast_sigmoid(x1);
                    r.z = fast_sigmoid(x2);
                    r.w = fast_sigmoid(x3);
                    op[g * 32 + lane] = r;
                }
            }
        }
    }
}

extern "C" void kernel_launch(void* const* d_in, const int* in_sizes, int n_in,
                              void* d_out, int out_size) {
    // Map inputs by element count (all distinct): V=802816, A=1048576, w=16, b=1
    const float* V = nullptr; const float* A = nullptr;
    const float* w = nullptr; const float* bp = nullptr;
    for (int i = 0; i < n_in; ++i) {
        switch (in_sizes[i]) {
            case Bsz * Kc * HW: V  = (const float*)d_in[i]; break;  // 802816
            case Bsz * Kc * PQ: A  = (const float*)d_in[i]; break;  // 1048576
            case Kc:            w  = (const float*)d_in[i]; break;  // 16
            case 1:             bp = (const float*)d_in[i]; break;  // scalar
            default: break;
        }
    }
    float* out = (float*)d_out;
    // grid: x = hw-chunks of 64 (13 covers 784 with a short tail), y = pq halves, z = batch
    dim3 grid((HW + CH - 1) / CH, PQ / PQ_TILE, Bsz);
    fused_vaw_sigmoid_kernel<<<grid, THREADS>>>(V, A, w, bp, out);
}

// round 10
// speedup vs baseline: 3.2301x; 3.2301x over previous
#include <cuda_runtime.h>

typedef unsigned long long u64;

#define DEVINL __device__ __forceinline__

DEVINL u64 pack2(float lo, float hi) {
    u64 r; asm("mov.b64 %0, {%1,%2};" : "=l"(r) : "f"(lo), "f"(hi)); return r;
}
DEVINL void unpack2(u64 v, float& lo, float& hi) {
    asm("mov.b64 {%0,%1}, %2;" : "=f"(lo), "=f"(hi) : "l"(v));
}
DEVINL u64 ffma2(u64 a, u64 b, u64 c) {
    u64 d; asm("fma.rn.f32x2 %0, %1, %2, %3;" : "=l"(d) : "l"(a), "l"(b), "l"(c)); return d;
}
DEVINL u64 add2(u64 a, u64 b) {
    u64 d; asm("add.rn.f32x2 %0, %1, %2;" : "=l"(d) : "l"(a), "l"(b)); return d;
}
DEVINL float ex2f(float x) { float t; asm("ex2.approx.f32 %0, %1;" : "=f"(t) : "f"(x)); return t; }
DEVINL float rcpf(float x) { float t; asm("rcp.approx.f32 %0, %1;" : "=f"(t) : "f"(x)); return t; }

static constexpr int Bsz = 64;
static constexpr int Kc  = 16;
static constexpr int HW  = 784;    // 28*28
static constexpr int PQ  = 1024;   // 32*32
static constexpr int THREADS = 256;  // each thread owns 4 pq columns (full PQ per CTA)
static constexpr int CH      = 56;   // hw rows per CTA; 784 = 14*56, no tail

__global__ __launch_bounds__(THREADS, 2)
void fused_vaw_sigmoid_kernel(
    const float* __restrict__ V,      // [B,K,HW]
    const float* __restrict__ A,      // [B,K,PQ]
    const float* __restrict__ w,      // [K]
    const float* __restrict__ bias_p, // [1]
    float* __restrict__ out)          // [B,HW,PQ]
{
    // V values for this hw-chunk, duplicated as (v,v) f32x2 pairs: 56*16*8B = 7 KB
    __shared__ alignas(16) u64 sV[CH * Kc];

    const int tid = threadIdx.x;
    const int b   = blockIdx.y;
    const int hw0 = blockIdx.x * CH;

    const float NLOG2E = -1.4426950408889634f;   // fold -log2(e) into w and bias

    // ---- A tile (scaled by -log2(e)*w_k) lives in REGISTERS for the whole CTA ----
    // thread t owns pq = 4t..4t+3; a[k][0]=(pq0,pq1), a[k][1]=(pq2,pq3)
    u64 a[Kc][2];
    {
        const float4* A4 = reinterpret_cast<const float4*>(A) + (size_t)b * Kc * (PQ / 4);
        #pragma unroll
        for (int k = 0; k < Kc; ++k) {
            float wk = NLOG2E * __ldg(w + k);
            float4 av = __ldg(&A4[k * (PQ / 4) + tid]);
            a[k][0] = pack2(av.x * wk, av.y * wk);
            a[k][1] = pack2(av.z * wk, av.w * wk);
        }
    }

    // ---- stage V[b,:,hw0:hw0+56] into smem as dup pairs ----
    {
        const float* Vb = V + (size_t)b * Kc * HW + hw0;
        for (int idx = tid; idx < CH * Kc; idx += THREADS) {
            int k   = idx / CH;           // consecutive tid -> consecutive hw (coalesced runs)
            int hwl = idx - k * CH;
            float v = __ldg(&Vb[k * HW + hwl]);
            sV[hwl * Kc + k] = pack2(v, v);
        }
    }
    __syncthreads();

    const float biasv = NLOG2E * __ldg(bias_p);
    const u64 bias2 = pack2(biasv, biasv);
    const u64 zero2 = pack2(0.0f, 0.0f);

    float4* orow = reinterpret_cast<float4*>(out + (size_t)(b * HW + hw0) * PQ) + tid;

    #pragma unroll 2
    for (int r = 0; r < CH; ++r) {
        const ulonglong2* vp = reinterpret_cast<const ulonglong2*>(&sV[r * Kc]);

        // 4 independent accumulation chains (2 pq-pairs x 2 k-partials)
        u64 ac00 = bias2, ac01 = bias2;   // k even
        u64 ac10 = zero2, ac11 = zero2;   // k odd
        #pragma unroll
        for (int kk = 0; kk < Kc / 2; ++kk) {
            ulonglong2 v2 = vp[kk];       // LDS.128 broadcast: dup pairs for k=2kk, 2kk+1
            ac00 = ffma2(v2.x, a[2 * kk + 0][0], ac00);
            ac01 = ffma2(v2.x, a[2 * kk + 0][1], ac01);
            ac10 = ffma2(v2.y, a[2 * kk + 1][0], ac10);
            ac11 = ffma2(v2.y, a[2 * kk + 1][1], ac11);
        }
        u64 s0 = add2(ac00, ac10);
        u64 s1 = add2(ac01, ac11);

        // sigmoid(x) = 1 / (1 + 2^(-log2e * x));  acc already = -log2e*(x + bias)
        float x0, x1, x2, x3;
        unpack2(s0, x0, x1);
        unpack2(s1, x2, x3);
        float4 rv;
        rv.x = rcpf(1.0f + ex2f(x0));
        rv.y = rcpf(1.0f + ex2f(x1));
        rv.z = rcpf(1.0f + ex2f(x2));
        rv.w = rcpf(1.0f + ex2f(x3));

        orow[(size_t)r * (PQ / 4)] = rv;
    }
}

extern "C" void kernel_launch(void* const* d_in, const int* in_sizes, int n_in,
                              void* d_out, int out_size) {
    // Map inputs by element count (all distinct): V=802816, A=1048576, w=16, b=1
    const float* V = nullptr; const float* A = nullptr;
    const float* w = nullptr; const float* bp = nullptr;
    for (int i = 0; i < n_in; ++i) {
        switch (in_sizes[i]) {
            case Bsz * Kc * HW: V  = (const float*)d_in[i]; break;  // 802816
            case Bsz * Kc * PQ: A  = (const float*)d_in[i]; break;  // 1048576
            case Kc:            w  = (const float*)d_in[i]; break;  // 16
            case 1:             bp = (const float*)d_in[i]; break;  // scalar
            default: break;
        }
    }
    float* out = (float*)d_out;
    dim3 grid(HW / CH, Bsz);   // (14, 64) = 896 CTAs
    fused_vaw_sigmoid_kernel<<<grid, THREADS>>>(V, A, w, bp, out);
}

// round 12
// speedup vs baseline: 3.7653x; 1.1657x over previous
#include <cuda_runtime.h>

typedef unsigned long long u64;

#define DEVINL __device__ __forceinline__

DEVINL u64 pack2(float lo, float hi) {
    u64 r; asm("mov.b64 %0, {%1,%2};" : "=l"(r) : "f"(lo), "f"(hi)); return r;
}
DEVINL void unpack2(u64 v, float& lo, float& hi) {
    asm("mov.b64 {%0,%1}, %2;" : "=f"(lo), "=f"(hi) : "l"(v));
}
DEVINL u64 ffma2(u64 a, u64 b, u64 c) {
    u64 d; asm("fma.rn.f32x2 %0, %1, %2, %3;" : "=l"(d) : "l"(a), "l"(b), "l"(c)); return d;
}
DEVINL u64 add2(u64 a, u64 b) {
    u64 d; asm("add.rn.f32x2 %0, %1, %2;" : "=l"(d) : "l"(a), "l"(b)); return d;
}
DEVINL float tanhf_approx(float x) {
    float t; asm("tanh.approx.f32 %0, %1;" : "=f"(t) : "f"(x)); return t;
}

static constexpr int Bsz = 64;
static constexpr int Kc  = 16;
static constexpr int HW  = 784;    // 28*28
static constexpr int PQ  = 1024;   // 32*32
static constexpr int THREADS = 256;  // each thread owns 4 pq columns (full PQ per CTA)
static constexpr int CH      = 56;   // hw rows per CTA; 784 = 14*56, no tail

__global__ __launch_bounds__(THREADS, 2)
void fused_vaw_sigmoid_kernel(
    const float* __restrict__ V,      // [B,K,HW]
    const float* __restrict__ A,      // [B,K,PQ]
    const float* __restrict__ w,      // [K]
    const float* __restrict__ bias_p, // [1]
    float* __restrict__ out)          // [B,HW,PQ]
{
    // V values for this hw-chunk, duplicated as (v,v) f32x2 pairs: 56*16*8B = 7 KB
    __shared__ alignas(16) u64 sV[CH * Kc];

    const int tid = threadIdx.x;
    const int b   = blockIdx.y;
    const int hw0 = blockIdx.x * CH;

    const float HALF = 0.5f;   // sigmoid(y) = 0.5 + 0.5*tanh(y/2): fold the /2 into w, bias

    // ---- A tile (scaled by 0.5*w_k) lives in REGISTERS for the whole CTA ----
    // thread t owns pq = 4t..4t+3; a[k][0]=(pq0,pq1), a[k][1]=(pq2,pq3)
    u64 a[Kc][2];
    {
        const float4* A4 = reinterpret_cast<const float4*>(A) + (size_t)b * Kc * (PQ / 4);
        #pragma unroll
        for (int k = 0; k < Kc; ++k) {
            float wk = HALF * __ldg(w + k);
            float4 av = __ldg(&A4[k * (PQ / 4) + tid]);
            a[k][0] = pack2(av.x * wk, av.y * wk);
            a[k][1] = pack2(av.z * wk, av.w * wk);
        }
    }

    // ---- stage V[b,:,hw0:hw0+56] into smem as dup pairs ----
    {
        const float* Vb = V + (size_t)b * Kc * HW + hw0;
        for (int idx = tid; idx < CH * Kc; idx += THREADS) {
            int k   = idx / CH;           // consecutive tid -> consecutive hw (coalesced runs)
            int hwl = idx - k * CH;
            float v = __ldg(&Vb[k * HW + hwl]);
            sV[hwl * Kc + k] = pack2(v, v);
        }
    }
    __syncthreads();

    const float biasv = HALF * __ldg(bias_p);
    const u64 bias2 = pack2(biasv, biasv);
    const u64 zero2 = pack2(0.0f, 0.0f);

    float4* orow = reinterpret_cast<float4*>(out + (size_t)(b * HW + hw0) * PQ) + tid;

    #pragma unroll 2
    for (int r = 0; r < CH; ++r) {
        const ulonglong2* vp = reinterpret_cast<const ulonglong2*>(&sV[r * Kc]);

        // 4 independent accumulation chains (2 pq-pairs x 2 k-partials)
        u64 ac00 = bias2, ac01 = bias2;   // k even
        u64 ac10 = zero2, ac11 = zero2;   // k odd
        #pragma unroll
        for (int kk = 0; kk < Kc / 2; ++kk) {
            ulonglong2 v2 = vp[kk];       // LDS.128 broadcast: dup pairs for k=2kk, 2kk+1
            ac00 = ffma2(v2.x, a[2 * kk + 0][0], ac00);
            ac01 = ffma2(v2.x, a[2 * kk + 0][1], ac01);
            ac10 = ffma2(v2.y, a[2 * kk + 1][0], ac10);
            ac11 = ffma2(v2.y, a[2 * kk + 1][1], ac11);
        }
        u64 s0 = add2(ac00, ac10);
        u64 s1 = add2(ac01, ac11);

        // acc = 0.5*(x + bias);  sigmoid = 0.5 + 0.5*tanh(acc)  (1 MUFU + 1 FFMA each)
        float x0, x1, x2, x3;
        unpack2(s0, x0, x1);
        unpack2(s1, x2, x3);
        float t0 = tanhf_approx(x0);
        float t1 = tanhf_approx(x1);
        float t2 = tanhf_approx(x2);
        float t3 = tanhf_approx(x3);
        float4 rv;
        rv.x = fmaf(t0, 0.5f, 0.5f);
        rv.y = fmaf(t1, 0.5f, 0.5f);
        rv.z = fmaf(t2, 0.5f, 0.5f);
        rv.w = fmaf(t3, 0.5f, 0.5f);

        orow[(size_t)r * (PQ / 4)] = rv;
    }
}

extern "C" void kernel_launch(void* const* d_in, const int* in_sizes, int n_in,
                              void* d_out, int out_size) {
    // Map inputs by element count (all distinct): V=802816, A=1048576, w=16, b=1
    const float* V = nullptr; const float* A = nullptr;
    const float* w = nullptr; const float* bp = nullptr;
    for (int i = 0; i < n_in; ++i) {
        switch (in_sizes[i]) {
            case Bsz * Kc * HW: V  = (const float*)d_in[i]; break;  // 802816
            case Bsz * Kc * PQ: A  = (const float*)d_in[i]; break;  // 1048576
            case Kc:            w  = (const float*)d_in[i]; break;  // 16
            case 1:             bp = (const float*)d_in[i]; break;  // scalar
            default: break;
        }
    }
    float* out = (float*)d_out;
    dim3 grid(HW / CH, Bsz);   // (14, 64) = 896 CTAs
    fused_vaw_sigmoid_kernel<<<grid, THREADS>>>(V, A, w, bp, out);
}

// round 16
// speedup vs baseline: 3.7922x; 1.0071x over previous
#include <cuda_runtime.h>

typedef unsigned long long u64;

#define DEVINL __device__ __forceinline__

DEVINL u64 pack2(float lo, float hi) {
    u64 r; asm("mov.b64 %0, {%1,%2};" : "=l"(r) : "f"(lo), "f"(hi)); return r;
}
DEVINL void unpack2(u64 v, float& lo, float& hi) {
    asm("mov.b64 {%0,%1}, %2;" : "=f"(lo), "=f"(hi) : "l"(v));
}
DEVINL u64 ffma2(u64 a, u64 b, u64 c) {
    u64 d; asm("fma.rn.f32x2 %0, %1, %2, %3;" : "=l"(d) : "l"(a), "l"(b), "l"(c)); return d;
}
DEVINL u64 add2(u64 a, u64 b) {
    u64 d; asm("add.rn.f32x2 %0, %1, %2;" : "=l"(d) : "l"(a), "l"(b)); return d;
}
DEVINL float tanhf_approx(float x) {
    float t; asm("tanh.approx.f32 %0, %1;" : "=f"(t) : "f"(x)); return t;
}

static constexpr int Bsz = 64;
static constexpr int Kc  = 16;
static constexpr int HW  = 784;    // 28*28
static constexpr int PQ  = 1024;   // 32*32
static constexpr int THREADS = 256;  // each thread owns 4 pq columns (full PQ per CTA)
static constexpr int CH_MAX  = 61;   // max hw rows per CTA (balanced-grid split)

// Balanced grid: 888 CTAs = 148 SMs * 2 CTAs/SM * 3 exact waves.
//   b in [0,56):  14 chunks x 56 rows  -> 784 CTAs
//   b in [56,64): 13 chunks (4x61 + 9x60 = 784 rows) -> 104 CTAs
static constexpr int GRID_CTAS = 888;

__global__ __launch_bounds__(THREADS, 2)
void fused_vaw_sigmoid_kernel(
    const float* __restrict__ V,      // [B,K,HW]
    const float* __restrict__ A,      // [B,K,PQ]
    const float* __restrict__ w,      // [K]
    const float* __restrict__ bias_p, // [1]
    float* __restrict__ out)          // [B,HW,PQ]
{
    // V values for this hw-chunk, duplicated as (v,v) f32x2 pairs: up to 61*16*8B < 8 KB
    __shared__ alignas(16) u64 sV[CH_MAX * Kc];

    const int tid = threadIdx.x;

    // ---- balanced tile mapping ----
    int b, start, len;
    {
        const int c = blockIdx.x;
        if (c < 784) {               // 56 b's with 14 chunks of 56
            b = c / 14;
            const int j = c - b * 14;
            start = j * 56;
            len = 56;
        } else {                     // 8 b's with 13 chunks: 4x61 + 9x60
            const int cc = c - 784;
            const int bb = cc / 13;
            const int j  = cc - bb * 13;
            b = 56 + bb;
            if (j < 4) { start = j * 61;            len = 61; }
            else       { start = 244 + (j - 4) * 60; len = 60; }
        }
    }

    const float HALF = 0.5f;   // sigmoid(y) = 0.5 + 0.5*tanh(y/2): fold the /2 into w, bias

    // ---- A tile (scaled by 0.5*w_k) lives in REGISTERS for the whole CTA ----
    // thread t owns pq = 4t..4t+3; a[k][0]=(pq0,pq1), a[k][1]=(pq2,pq3)
    u64 a[Kc][2];
    {
        const float4* A4 = reinterpret_cast<const float4*>(A) + (size_t)b * Kc * (PQ / 4);
        #pragma unroll
        for (int k = 0; k < Kc; ++k) {
            float wk = HALF * __ldg(w + k);
            float4 av = __ldg(&A4[k * (PQ / 4) + tid]);
            a[k][0] = pack2(av.x * wk, av.y * wk);
            a[k][1] = pack2(av.z * wk, av.w * wk);
        }
    }

    // ---- stage V[b,:,start:start+len] into smem as dup pairs ----
    {
        const float* Vb = V + (size_t)b * Kc * HW + start;
        const int total = len * Kc;
        for (int idx = tid; idx < total; idx += THREADS) {
            int k   = idx / len;          // consecutive tid -> consecutive hw (coalesced runs)
            int hwl = idx - k * len;
            float v = __ldg(&Vb[k * HW + hwl]);
            sV[hwl * Kc + k] = pack2(v, v);
        }
    }
    __syncthreads();

    const float biasv = HALF * __ldg(bias_p);
    const u64 bias2 = pack2(biasv, biasv);
    const u64 zero2 = pack2(0.0f, 0.0f);

    float4* orow = reinterpret_cast<float4*>(out + (size_t)(b * HW + start) * PQ) + tid;

    #pragma unroll 2
    for (int r = 0; r < len; ++r) {
        const ulonglong2* vp = reinterpret_cast<const ulonglong2*>(&sV[r * Kc]);

        // 4 independent accumulation chains (2 pq-pairs x 2 k-partials)
        u64 ac00 = bias2, ac01 = bias2;   // k even
        u64 ac10 = zero2, ac11 = zero2;   // k odd
        #pragma unroll
        for (int kk = 0; kk < Kc / 2; ++kk) {
            ulonglong2 v2 = vp[kk];       // LDS.128 broadcast: dup pairs for k=2kk, 2kk+1
            ac00 = ffma2(v2.x, a[2 * kk + 0][0], ac00);
            ac01 = ffma2(v2.x, a[2 * kk + 0][1], ac01);
            ac10 = ffma2(v2.y, a[2 * kk + 1][0], ac10);
            ac11 = ffma2(v2.y, a[2 * kk + 1][1], ac11);
        }
        u64 s0 = add2(ac00, ac10);
        u64 s1 = add2(ac01, ac11);

        // acc = 0.5*(x + bias);  sigmoid = 0.5 + 0.5*tanh(acc)  (1 MUFU + 1 FFMA each)
        float x0, x1, x2, x3;
        unpack2(s0, x0, x1);
        unpack2(s1, x2, x3);
        float t0 = tanhf_approx(x0);
        float t1 = tanhf_approx(x1);
        float t2 = tanhf_approx(x2);
        float t3 = tanhf_approx(x3);
        float4 rv;
        rv.x = fmaf(t0, 0.5f, 0.5f);
        rv.y = fmaf(t1, 0.5f, 0.5f);
        rv.z = fmaf(t2, 0.5f, 0.5f);
        rv.w = fmaf(t3, 0.5f, 0.5f);

        orow[(size_t)r * (PQ / 4)] = rv;
    }
}

extern "C" void kernel_launch(void* const* d_in, const int* in_sizes, int n_in,
                              void* d_out, int out_size) {
    // Map inputs by element count (all distinct): V=802816, A=1048576, w=16, b=1
    const float* V = nullptr; const float* A = nullptr;
    const float* w = nullptr; const float* bp = nullptr;
    for (int i = 0; i < n_in; ++i) {
        switch (in_sizes[i]) {
            case Bsz * Kc * HW: V  = (const float*)d_in[i]; break;  // 802816
            case Bsz * Kc * PQ: A  = (const float*)d_in[i]; break;  // 1048576
            case Kc:            w  = (const float*)d_in[i]; break;  // 16
            case 1:             bp = (const float*)d_in[i]; break;  // scalar
            default: break;
        }
    }
    float* out = (float*)d_out;
    fused_vaw_sigmoid_kernel<<<GRID_CTAS, THREADS>>>(V, A, w, bp, out);
}